// round 12
// baseline (speedup 1.0000x reference)
#include <cuda_runtime.h>
#include <math.h>
#include <stdint.h>

// out[i] = sum_{j<512} r[batch[i][j]] + log(n_pos / n_neg)
//
// Dual-path index delivery (LDG path caps at ~14 B/cyc/SM concurrency):
//  - r (201KB) staged to SMEM via TMA (critical path, issued first).
//  - 63 rows/CTA via LDG register preload (warps 7..15, 7 rows each).
//  - 47/48 rows/CTA via cp.async.bulk into 14x2KB slots: warps 0..6 are
//    self-producing consumers, each with a private depth-2 slot ring
//    (lane 0 reissues the slot's next tile right after the warp consumes).
// 148 CTAs x 512 threads. CTA b owns rows [start_b, start_b+cnt_b).

#define ROWS   16384
#define LEN    512
#define VOCAB  50257
#define NBLK   148
#define NTHR   512
#define NCONS  7                     // consumer warps (0..6)
#define NLDGW  9                     // LDG warps (7..15), 7 rows each
#define LROWS  (NLDGW * 7)           // 63
#define ROW_BYTES 2048

#define RS_BULK   ((VOCAB * 4 / 16) * 16)    // 201024
#define RBAR_OFF  201040
#define TMBAR(s)  (201048 + (s) * 8)         // 14 slot barriers
#define SLOT(s)   (201216 + (s) * ROW_BYTES) // 128B-aligned slots
#define SMEM_TOTAL (201216 + 14 * ROW_BYTES) // 229888 <= 232448

__device__ __forceinline__ uint32_t smem_u32(const void* p) {
    uint32_t a;
    asm("{ .reg .u64 t; cvta.to.shared.u64 t, %1; cvt.u32.u64 %0, t; }"
        : "=r"(a) : "l"(p));
    return a;
}
__device__ __forceinline__ void bar_init(uint32_t bar, uint32_t cnt) {
    asm volatile("mbarrier.init.shared.b64 [%0], %1;" :: "r"(bar), "r"(cnt) : "memory");
}
__device__ __forceinline__ void bar_expect_tx(uint32_t bar, uint32_t bytes) {
    asm volatile("mbarrier.arrive.expect_tx.shared.b64 _, [%0], %1;"
                 :: "r"(bar), "r"(bytes) : "memory");
}
__device__ __forceinline__ void bar_wait(uint32_t bar, uint32_t parity) {
    uint32_t done;
    asm volatile(
        "{ .reg .pred p;\n"
        "  mbarrier.try_wait.parity.acquire.cta.shared::cta.b64 p, [%1], %2;\n"
        "  selp.b32 %0, 1, 0, p; }"
        : "=r"(done) : "r"(bar), "r"(parity) : "memory");
    while (!done) {
        asm volatile(
            "{ .reg .pred p;\n"
            "  mbarrier.try_wait.parity.acquire.cta.shared::cta.b64 p, [%1], %2, 0x989680;\n"
            "  selp.b32 %0, 1, 0, p; }"
            : "=r"(done) : "r"(bar), "r"(parity) : "memory");
    }
}
__device__ __forceinline__ void bulk_g2s(uint32_t dst, const void* src,
                                         uint32_t bytes, uint32_t bar) {
    asm volatile(
        "cp.async.bulk.shared::cta.global.mbarrier::complete_tx::bytes "
        "[%0], [%1], %2, [%3];"
        :: "r"(dst), "l"(src), "r"(bytes), "r"(bar) : "memory");
}
__device__ __forceinline__ void load_row(const int* __restrict__ batch,
                                         int row, int lane, int4* v)
{
    const int4* __restrict__ bp =
        reinterpret_cast<const int4*>(batch + (size_t)row * LEN);
#pragma unroll
    for (int i = 0; i < 4; i++)
        v[i] = __ldcg(bp + lane + 32 * i);
}
__device__ __forceinline__ void compute_pair(const float* __restrict__ rs,
                                             const int4* x, const int4* y,
                                             int lane, float lp,
                                             float* __restrict__ out,
                                             int row0, int row1)
{
    float a0 = 0.f, b0 = 0.f, a1 = 0.f, b1 = 0.f;
#pragma unroll
    for (int i = 0; i < 4; i++) {
        a0 += rs[x[i].x];  b0 += rs[x[i].y];
        a0 += rs[x[i].z];  b0 += rs[x[i].w];
        a1 += rs[y[i].x];  b1 += rs[y[i].y];
        a1 += rs[y[i].z];  b1 += rs[y[i].w];
    }
    float s0 = a0 + b0;
    float s1 = a1 + b1;
#pragma unroll
    for (int o = 16; o > 0; o >>= 1) {
        s0 += __shfl_xor_sync(0xFFFFFFFFu, s0, o);
        s1 += __shfl_xor_sync(0xFFFFFFFFu, s1, o);
    }
    if (lane == 0) {
        out[row0] = s0 + lp;
        out[row1] = s1 + lp;
    }
}

__global__ __launch_bounds__(NTHR, 1) void nb_dp_kernel(
    const int* __restrict__ batch,
    const float* __restrict__ r,
    const int* __restrict__ n_pos,
    const int* __restrict__ n_neg,
    float* __restrict__ out)
{
    extern __shared__ float rs[];
    char* sm = reinterpret_cast<char*>(rs);

    const int tid  = threadIdx.x;
    const int warp = tid >> 5;
    const int lane = tid & 31;
    const int b    = blockIdx.x;

    const int cnt   = 110 + (b < 104);
    const int start = b * 110 + (b < 104 ? b : 104);
    const int T     = cnt - LROWS;               // 47 or 48 TMA rows

    const uint32_t rs_s = smem_u32(sm);
    const uint32_t rbar = smem_u32(sm + RBAR_OFF);

    if (tid == 0) {
        rs[VOCAB - 1] = r[VOCAB - 1];            // 4B tail TMA can't cover
        bar_init(rbar, 1);
#pragma unroll
        for (int s = 0; s < 14; s++)
            bar_init(smem_u32(sm + TMBAR(s)), 1);
    }
    __syncthreads();

    // ---- Stage r via TMA (critical path, issued first) ----
    if (tid == 0) {
        bar_expect_tx(rbar, (uint32_t)RS_BULK);
        const uint32_t chunk = RS_BULK / 4;
#pragma unroll
        for (int i = 0; i < 4; i++)
            bulk_g2s(rs_s + i * chunk, (const char*)r + i * chunk, chunk, rbar);
    }

    const float lp = logf((float)__ldg(n_pos) / (float)__ldg(n_neg));

    if (warp < NCONS) {
        // ================= Consumers: self-producing depth-2 ring =========
        const int w = warp;
        const uint32_t mb0 = smem_u32(sm + TMBAR(2 * w));
        const uint32_t mb1 = smem_u32(sm + TMBAR(2 * w + 1));
        const uint32_t sl0 = smem_u32(sm + SLOT(2 * w));
        const uint32_t sl1 = smem_u32(sm + SLOT(2 * w + 1));
        const int4* __restrict__ buf0 = reinterpret_cast<const int4*>(sm + SLOT(2 * w));
        const int4* __restrict__ buf1 = reinterpret_cast<const int4*>(sm + SLOT(2 * w + 1));

        // Prologue: fill both slots (tiles k=0,1 -> rows start+w, start+w+7).
        if (lane == 0) {
            if (w < T) {
                bar_expect_tx(mb0, ROW_BYTES);
                bulk_g2s(sl0, (const char*)batch + (size_t)(start + w) * ROW_BYTES,
                         ROW_BYTES, mb0);
            }
            if (w + 7 < T) {
                bar_expect_tx(mb1, ROW_BYTES);
                bulk_g2s(sl1, (const char*)batch + (size_t)(start + w + 7) * ROW_BYTES,
                         ROW_BYTES, mb1);
            }
        }

        bar_wait(rbar, 0);                       // r resident before gathers

        for (int k = 0; w + 7 * k < T; k++) {
            const int s = k & 1;
            bar_wait(s ? mb1 : mb0, (k >> 1) & 1);

            const int4* __restrict__ bp = s ? buf1 : buf0;
            float a = 0.f, c = 0.f;
#pragma unroll
            for (int i = 0; i < 4; i++) {
                int4 v = bp[lane + 32 * i];
                a += rs[v.x];  c += rs[v.y];
                a += rs[v.z];  c += rs[v.w];
            }
            float sum = a + c;
            __syncwarp();                        // all lanes done reading slot

            // Reissue this slot for tile k+2 (copy-ahead depth 2).
            const int nrow = w + 7 * (k + 2);
            if (lane == 0 && nrow < T) {
                asm volatile("fence.proxy.async.shared::cta;" ::: "memory");
                bar_expect_tx(s ? mb1 : mb0, ROW_BYTES);
                bulk_g2s(s ? sl1 : sl0,
                         (const char*)batch + (size_t)(start + nrow) * ROW_BYTES,
                         ROW_BYTES, s ? mb1 : mb0);
            }

#pragma unroll
            for (int o = 16; o > 0; o >>= 1)
                sum += __shfl_xor_sync(0xFFFFFFFFu, sum, o);
            if (lane == 0)
                out[start + w + 7 * k] = sum + lp;
        }
    } else {
        // ================= LDG warps: 7 register-preloaded rows ============
        const int base = start + T + (warp - NCONS) * 7;

        int4 A[4], B[4], C[4], D[4], E[4], F[4];
        load_row(batch, base + 0, lane, A);
        load_row(batch, base + 1, lane, B);
        load_row(batch, base + 2, lane, C);
        load_row(batch, base + 3, lane, D);
        load_row(batch, base + 4, lane, E);
        load_row(batch, base + 5, lane, F);

        bar_wait(rbar, 0);

        compute_pair(rs, A, B, lane, lp, out, base + 0, base + 1);

        int4 G[4];                               // 7th row reuses dead regs
        load_row(batch, base + 6, lane, G);

        compute_pair(rs, C, D, lane, lp, out, base + 2, base + 3);
        compute_pair(rs, E, F, lane, lp, out, base + 4, base + 5);

        float a = 0.f, c = 0.f;
#pragma unroll
        for (int i = 0; i < 4; i++) {
            a += rs[G[i].x];  c += rs[G[i].y];
            a += rs[G[i].z];  c += rs[G[i].w];
        }
        float s = a + c;
#pragma unroll
        for (int o = 16; o > 0; o >>= 1)
            s += __shfl_xor_sync(0xFFFFFFFFu, s, o);
        if (lane == 0)
            out[base + 6] = s + lp;
    }
}

extern "C" void kernel_launch(void* const* d_in, const int* in_sizes, int n_in,
                              void* d_out, int out_size)
{
    const int*   batch = (const int*)  d_in[0];
    const float* r     = (const float*)d_in[1];
    const int*   npos  = (const int*)  d_in[2];
    const int*   nneg  = (const int*)  d_in[3];
    float*       out   = (float*)      d_out;

    static int configured = 0;
    if (!configured) {
        cudaFuncSetAttribute(nb_dp_kernel,
                             cudaFuncAttributeMaxDynamicSharedMemorySize,
                             SMEM_TOTAL);
        configured = 1;
    }

    nb_dp_kernel<<<NBLK, NTHR, SMEM_TOTAL>>>(batch, r, npos, nneg, out);
}

// round 13
// speedup vs baseline: 1.0200x; 1.0200x over previous
#include <cuda_runtime.h>
#include <math.h>
#include <stdint.h>

// out[i] = sum_{j<512} r[batch[i][j]] + log(n_pos / n_neg)
//
// Key fix vs R6: cp.async.bulk.prefetch.L2 on the whole index block.
// The LDG path is capped by ~45 outstanding lines/SM; throughput =
// lines*128B/latency. Prefetching indices DRAM->L2 (bulk engine, no MSHR
// cost) turns the LDGs into L2 hits (~250cyc vs 577), ~2.3x the stream rate.
// r (201KB) staged to SMEM via TMA; pair-rotated gather pipeline after.
// 148 CTAs x 512 threads (16 warps).

#define ROWS   16384
#define LEN    512
#define VOCAB  50257
#define NBLK   148
#define NTHR   512
#define NWARP  (NTHR / 32)           // 16
#define GWARPS (NBLK * NWARP)        // 2368;  ROWS = 6*GWARPS + 2176
#define ROW_BYTES 2048

#define RS_BULK    ((VOCAB * 4 / 16) * 16)   // 201024
#define MBAR_OFF   201040
#define SMEM_TOTAL (MBAR_OFF + 16)

__device__ __forceinline__ uint32_t smem_u32(const void* p) {
    uint32_t a;
    asm("{ .reg .u64 t; cvta.to.shared.u64 t, %1; cvt.u32.u64 %0, t; }"
        : "=r"(a) : "l"(p));
    return a;
}

__device__ __forceinline__ void load_row(const int* __restrict__ batch,
                                         int row, int lane, int4* v)
{
    const int4* __restrict__ bp =
        reinterpret_cast<const int4*>(batch + (size_t)row * LEN);
#pragma unroll
    for (int i = 0; i < 4; i++)
        v[i] = bp[lane + 32 * i];
}

__device__ __forceinline__ void compute_pair(const float* __restrict__ rs,
                                             const int4* x, const int4* y,
                                             int lane, float lp,
                                             float* __restrict__ out,
                                             int row0, int row1)
{
    float a0 = 0.f, b0 = 0.f, a1 = 0.f, b1 = 0.f;
#pragma unroll
    for (int i = 0; i < 4; i++) {
        a0 += rs[x[i].x];  b0 += rs[x[i].y];
        a0 += rs[x[i].z];  b0 += rs[x[i].w];
        a1 += rs[y[i].x];  b1 += rs[y[i].y];
        a1 += rs[y[i].z];  b1 += rs[y[i].w];
    }
    float s0 = a0 + b0;
    float s1 = a1 + b1;
#pragma unroll
    for (int o = 16; o > 0; o >>= 1) {
        s0 += __shfl_xor_sync(0xFFFFFFFFu, s0, o);
        s1 += __shfl_xor_sync(0xFFFFFFFFu, s1, o);
    }
    if (lane == 0) {
        out[row0] = s0 + lp;
        out[row1] = s1 + lp;
    }
}

__global__ __launch_bounds__(NTHR, 1) void nb_pf_kernel(
    const int* __restrict__ batch,
    const float* __restrict__ r,
    const int* __restrict__ n_pos,
    const int* __restrict__ n_neg,
    float* __restrict__ out)
{
    extern __shared__ float rs[];
    const int tid  = threadIdx.x;
    const int warp = tid >> 5;
    const int lane = tid & 31;
    const int gw   = blockIdx.x * NWARP + warp;

    char* smem_raw = reinterpret_cast<char*>(rs);
    const uint32_t mbar = smem_u32(smem_raw + MBAR_OFF);
    const uint32_t rs_s = smem_u32(smem_raw);

    const bool has7 = (gw + 6 * GWARPS) < ROWS;   // gw < 2176

    if (tid == 0) {
        rs[VOCAB - 1] = r[VOCAB - 1];
        asm volatile("mbarrier.init.shared.b64 [%0], %1;" :: "r"(mbar), "r"(1) : "memory");
    }

    // ---- L2 prefetch of this warp's ENTIRE index block (bulk engine,
    //      no MSHR / SMEM cost). Lane k prefetches row k. ----
    if (lane < 6 || (lane == 6 && has7)) {
        const char* src = (const char*)batch + (size_t)(gw + lane * GWARPS) * ROW_BYTES;
        asm volatile("cp.async.bulk.prefetch.L2.global [%0], %1;"
                     :: "l"(src), "r"((uint32_t)ROW_BYTES) : "memory");
    }

    __syncthreads();

    // ---- TMA bulk staging of r into SMEM ----
    if (tid == 0) {
        asm volatile("mbarrier.arrive.expect_tx.shared.b64 _, [%0], %1;"
                     :: "r"(mbar), "r"((uint32_t)RS_BULK) : "memory");
        const uint32_t chunk = RS_BULK / 4;
#pragma unroll
        for (int i = 0; i < 4; i++) {
            asm volatile(
                "cp.async.bulk.shared::cta.global.mbarrier::complete_tx::bytes "
                "[%0], [%1], %2, [%3];"
                :: "r"(rs_s + i * chunk),
                   "l"((const char*)r + i * chunk),
                   "r"(chunk), "r"(mbar)
                : "memory");
        }
    }

    // ---- Pre-issue only pair A,B (needed first; rest will be L2 hits) ----
    int4 A[4], B[4];
    load_row(batch, gw + 0 * GWARPS, lane, A);
    load_row(batch, gw + 1 * GWARPS, lane, B);

    const float lp = logf((float)__ldg(n_pos) / (float)__ldg(n_neg));

    // ---- Wait for r (acquire); prefetches land in L2 during this window ----
    {
        uint32_t done;
        asm volatile(
            "{ .reg .pred p;\n"
            "  mbarrier.try_wait.parity.acquire.cta.shared::cta.b64 p, [%1], %2;\n"
            "  selp.b32 %0, 1, 0, p; }"
            : "=r"(done) : "r"(mbar), "r"(0u) : "memory");
        if (!done) {
            asm volatile(
                "{ .reg .pred P1;\n"
                "WAIT_LOOP:\n"
                "  mbarrier.try_wait.parity.acquire.cta.shared::cta.b64 P1, [%0], %1, 0x989680;\n"
                "  @P1 bra.uni WAIT_DONE;\n"
                "  bra.uni WAIT_LOOP;\n"
                "WAIT_DONE: }"
                :: "r"(mbar), "r"(0u) : "memory");
        }
    }

    // ---- Pair-rotated compute; next pair's loads are L2 hits hidden
    //      behind the current pair's gather work ----
    int4 C[4], D[4];
    load_row(batch, gw + 2 * GWARPS, lane, C);
    load_row(batch, gw + 3 * GWARPS, lane, D);

    compute_pair(rs, A, B, lane, lp, out, gw + 0 * GWARPS, gw + 1 * GWARPS);

    int4 E[4], F[4];
    load_row(batch, gw + 4 * GWARPS, lane, E);
    load_row(batch, gw + 5 * GWARPS, lane, F);

    compute_pair(rs, C, D, lane, lp, out, gw + 2 * GWARPS, gw + 3 * GWARPS);

    int4 G[4];
    if (has7) load_row(batch, gw + 6 * GWARPS, lane, G);

    compute_pair(rs, E, F, lane, lp, out, gw + 4 * GWARPS, gw + 5 * GWARPS);

    if (has7) {
        float a = 0.f, b = 0.f;
#pragma unroll
        for (int i = 0; i < 4; i++) {
            a += rs[G[i].x];  b += rs[G[i].y];
            a += rs[G[i].z];  b += rs[G[i].w];
        }
        float s = a + b;
#pragma unroll
        for (int o = 16; o > 0; o >>= 1)
            s += __shfl_xor_sync(0xFFFFFFFFu, s, o);
        if (lane == 0)
            out[gw + 6 * GWARPS] = s + lp;
    }
}

extern "C" void kernel_launch(void* const* d_in, const int* in_sizes, int n_in,
                              void* d_out, int out_size)
{
    const int*   batch = (const int*)  d_in[0];
    const float* r     = (const float*)d_in[1];
    const int*   npos  = (const int*)  d_in[2];
    const int*   nneg  = (const int*)  d_in[3];
    float*       out   = (float*)      d_out;

    static int configured = 0;
    if (!configured) {
        cudaFuncSetAttribute(nb_pf_kernel,
                             cudaFuncAttributeMaxDynamicSharedMemorySize,
                             SMEM_TOTAL);
        configured = 1;
    }

    nb_pf_kernel<<<NBLK, NTHR, SMEM_TOTAL>>>(batch, r, npos, nneg, out);
}

// round 14
// speedup vs baseline: 1.0226x; 1.0025x over previous
#include <cuda_runtime.h>
#include <math.h>
#include <stdint.h>

// out[i] = sum_{j<512} r[batch[i][j]] + log(n_pos / n_neg)
//
// Index delivery via cp.async (LDGSTS): unlike LDG, its outstanding-op
// tracking is group-based ("depth cap NONE"), bypassing the ~45-line/SM
// MSHR cap that pinned every LDG/TMA variant at ~2.6TB/s. Each lane
// cp.asyncs exactly the 32B it later reads -> per-lane depth-2 pipeline
// with zero cross-lane sync (wait_group = cheap DEPBAR, no mbarriers).
//
// r (201KB) staged to SMEM via TMA by warp 15, which also computes the
// CTA's last 6 rows via the proven LDG-register path. Warps 0..14 stream
// the remaining rows (7 each) through 2x1KB chunk buffers.
// 148 CTAs x 512 threads. CTA b owns rows [start_b, start_b+cnt_b).

#define ROWS   16384
#define LEN    512
#define VOCAB  50257
#define NBLK   148
#define NTHR   512
#define CW     15                    // cp.async compute warps
#define L15R   6                     // rows handled by warp 15 via LDG

#define RS_BULK   ((VOCAB * 4 / 16) * 16)    // 201024
#define RBAR_OFF  201040
#define BUF(w,s)  (201088 + ((w) * 2 + (s)) * 1024)
#define SMEM_TOTAL (201088 + CW * 2 * 1024)  // 231808 <= 232448

__device__ __forceinline__ uint32_t smem_u32(const void* p) {
    uint32_t a;
    asm("{ .reg .u64 t; cvta.to.shared.u64 t, %1; cvt.u32.u64 %0, t; }"
        : "=r"(a) : "l"(p));
    return a;
}
__device__ __forceinline__ void bar_wait(uint32_t bar, uint32_t parity) {
    uint32_t done;
    asm volatile(
        "{ .reg .pred p;\n"
        "  mbarrier.try_wait.parity.acquire.cta.shared::cta.b64 p, [%1], %2;\n"
        "  selp.b32 %0, 1, 0, p; }"
        : "=r"(done) : "r"(bar), "r"(parity) : "memory");
    while (!done) {
        asm volatile(
            "{ .reg .pred p;\n"
            "  mbarrier.try_wait.parity.acquire.cta.shared::cta.b64 p, [%1], %2, 0x989680;\n"
            "  selp.b32 %0, 1, 0, p; }"
            : "=r"(done) : "r"(bar), "r"(parity) : "memory");
    }
}
// One 1KB chunk: this lane copies its own two int4 slots (lane, lane+32).
__device__ __forceinline__ void issue_chunk(uint32_t dst, const char* src) {
    asm volatile(
        "cp.async.cg.shared.global [%0], [%1], 16;\n\t"
        "cp.async.cg.shared.global [%2], [%3], 16;\n\t"
        "cp.async.commit_group;"
        :: "r"(dst), "l"(src), "r"(dst + 512), "l"(src + 512)
        : "memory");
}
__device__ __forceinline__ void load_row(const int* __restrict__ batch,
                                         int row, int lane, int4* v)
{
    const int4* __restrict__ bp =
        reinterpret_cast<const int4*>(batch + (size_t)row * LEN);
#pragma unroll
    for (int i = 0; i < 4; i++)
        v[i] = bp[lane + 32 * i];
}
__device__ __forceinline__ void compute_pair(const float* __restrict__ rs,
                                             const int4* x, const int4* y,
                                             int lane, float lp,
                                             float* __restrict__ out,
                                             int row0, int row1)
{
    float a0 = 0.f, b0 = 0.f, a1 = 0.f, b1 = 0.f;
#pragma unroll
    for (int i = 0; i < 4; i++) {
        a0 += rs[x[i].x];  b0 += rs[x[i].y];
        a0 += rs[x[i].z];  b0 += rs[x[i].w];
        a1 += rs[y[i].x];  b1 += rs[y[i].y];
        a1 += rs[y[i].z];  b1 += rs[y[i].w];
    }
    float s0 = a0 + b0;
    float s1 = a1 + b1;
#pragma unroll
    for (int o = 16; o > 0; o >>= 1) {
        s0 += __shfl_xor_sync(0xFFFFFFFFu, s0, o);
        s1 += __shfl_xor_sync(0xFFFFFFFFu, s1, o);
    }
    if (lane == 0) {
        out[row0] = s0 + lp;
        out[row1] = s1 + lp;
    }
}

__global__ __launch_bounds__(NTHR, 1) void nb_lgsts_kernel(
    const int* __restrict__ batch,
    const float* __restrict__ r,
    const int* __restrict__ n_pos,
    const int* __restrict__ n_neg,
    float* __restrict__ out)
{
    extern __shared__ float rs[];
    char* sm = reinterpret_cast<char*>(rs);

    const int tid  = threadIdx.x;
    const int warp = tid >> 5;
    const int lane = tid & 31;
    const int b    = blockIdx.x;

    const int cnt   = 110 + (b < 104);
    const int start = b * 110 + (b < 104 ? b : 104);
    const int cntc  = cnt - L15R;                // rows for cp.async warps

    const uint32_t rs_s = smem_u32(sm);
    const uint32_t rbar = smem_u32(sm + RBAR_OFF);

    if (tid == 0) {
        rs[VOCAB - 1] = r[VOCAB - 1];            // 4B tail TMA can't cover
        asm volatile("mbarrier.init.shared.b64 [%0], %1;" :: "r"(rbar), "r"(1) : "memory");
    }
    __syncthreads();

    const float lp = logf((float)__ldg(n_pos) / (float)__ldg(n_neg));

    if (warp == CW) {
        // ---- Warp 15: stage r via TMA, then 6 rows via LDG registers ----
        if (lane == 0) {
            asm volatile("mbarrier.arrive.expect_tx.shared.b64 _, [%0], %1;"
                         :: "r"(rbar), "r"((uint32_t)RS_BULK) : "memory");
            const uint32_t chunk = RS_BULK / 4;
#pragma unroll
            for (int i = 0; i < 4; i++)
                asm volatile(
                    "cp.async.bulk.shared::cta.global.mbarrier::complete_tx::bytes "
                    "[%0], [%1], %2, [%3];"
                    :: "r"(rs_s + i * chunk), "l"((const char*)r + i * chunk),
                       "r"(chunk), "r"(rbar) : "memory");
        }

        const int base = start + cntc;
        int4 A[4], B[4], C[4], D[4], E[4], F[4];
        load_row(batch, base + 0, lane, A);
        load_row(batch, base + 1, lane, B);
        load_row(batch, base + 2, lane, C);
        load_row(batch, base + 3, lane, D);
        load_row(batch, base + 4, lane, E);
        load_row(batch, base + 5, lane, F);

        bar_wait(rbar, 0);
        compute_pair(rs, A, B, lane, lp, out, base + 0, base + 1);
        compute_pair(rs, C, D, lane, lp, out, base + 2, base + 3);
        compute_pair(rs, E, F, lane, lp, out, base + 4, base + 5);
        return;
    }

    // ---- Warps 0..14: per-lane cp.async depth-2 chunk pipeline ----
    const int w = warp;
    // rows: start + w + 15k, k = 0..nrows-1;  chunks: 2 per row (1KB each)
    int nrows = 0;
    for (int k = 0; w + CW * k < cntc; k++) nrows++;
    const int C = 2 * nrows;

    const uint32_t d0 = smem_u32(sm + BUF(w, 0)) + lane * 16;
    const uint32_t d1 = smem_u32(sm + BUF(w, 1)) + lane * 16;
    const int4* __restrict__ b0 = reinterpret_cast<const int4*>(sm + BUF(w, 0));
    const int4* __restrict__ b1 = reinterpret_cast<const int4*>(sm + BUF(w, 1));
    const char* srcbase = (const char*)batch
                        + (size_t)(start + w) * 2048 + (size_t)lane * 16;
    // chunk c: src = srcbase + (c>>1)*15*2048 + (c&1)*1024

    // Prologue: chunks 0,1 in flight.
    issue_chunk(d0, srcbase);
    if (C > 1) issue_chunk(d1, srcbase + 1024);

    bar_wait(rbar, 0);                           // r resident before gathers

    float acc0 = 0.f, acc1 = 0.f;
#pragma unroll 1
    for (int c = 0; c < C; c++) {
        if (c == C - 1)
            asm volatile("cp.async.wait_group 0;" ::: "memory");
        else
            asm volatile("cp.async.wait_group 1;" ::: "memory");

        const int4* __restrict__ bp = (c & 1) ? b1 : b0;
        int4 va = bp[lane];
        int4 vb = bp[lane + 32];
        acc0 += rs[va.x];  acc1 += rs[va.y];
        acc0 += rs[va.z];  acc1 += rs[va.w];
        acc0 += rs[vb.x];  acc1 += rs[vb.y];
        acc0 += rs[vb.z];  acc1 += rs[vb.w];

        // Refill this buffer with chunk c+2 (indices consumed into regs).
        if (c + 2 < C)
            issue_chunk((c & 1) ? d1 : d0,
                        srcbase + (size_t)((c + 2) >> 1) * (CW * 2048)
                                + ((c & 1) ? 1024 : 0));

        if (c & 1) {                             // row complete -> reduce
            float s = acc0 + acc1;
#pragma unroll
            for (int o = 16; o > 0; o >>= 1)
                s += __shfl_xor_sync(0xFFFFFFFFu, s, o);
            if (lane == 0)
                out[start + w + CW * (c >> 1)] = s + lp;
            acc0 = 0.f;  acc1 = 0.f;
        }
    }
}

extern "C" void kernel_launch(void* const* d_in, const int* in_sizes, int n_in,
                              void* d_out, int out_size)
{
    const int*   batch = (const int*)  d_in[0];
    const float* r     = (const float*)d_in[1];
    const int*   npos  = (const int*)  d_in[2];
    const int*   nneg  = (const int*)  d_in[3];
    float*       out   = (float*)      d_out;

    static int configured = 0;
    if (!configured) {
        cudaFuncSetAttribute(nb_lgsts_kernel,
                             cudaFuncAttributeMaxDynamicSharedMemorySize,
                             SMEM_TOTAL);
        configured = 1;
    }

    nb_lgsts_kernel<<<NBLK, NTHR, SMEM_TOTAL>>>(batch, r, npos, nneg, out);
}